// round 8
// baseline (speedup 1.0000x reference)
#include <cuda_runtime.h>

static constexpr int Tn = 512;
static constexpr int Bn = 512;
static constexpr long BTn = (long)Bn * Tn;

// Scratch (device globals; allocation-free kernel_launch)
__device__ float g_xg[(size_t)512 * 512 * 288];   // max 4H = 288
__device__ float g_seqA[(size_t)512 * 512 * 64];  // e1 out / d1 out
__device__ float g_seqB[(size_t)512 * 512 * 32];  // e2 out

__device__ __forceinline__ float fsig(float x) {
    return __fdividef(1.0f, 1.0f + __expf(-x));
}
__device__ __forceinline__ float ftanh(float x) {
    return 1.0f - __fdividef(2.0f, __expf(2.0f * x) + 1.0f);
}

// ---- packed f32x2 helpers (Blackwell) ----
__device__ __forceinline__ unsigned long long pk2(float lo, float hi) {
    unsigned long long r;
    asm("mov.b64 %0, {%1, %2};" : "=l"(r) : "f"(lo), "f"(hi));
    return r;
}
__device__ __forceinline__ void upk2(unsigned long long v, float& lo, float& hi) {
    asm("mov.b64 {%0, %1}, %2;" : "=f"(lo), "=f"(hi) : "l"(v));
}
__device__ __forceinline__ unsigned long long ffma2(
    unsigned long long a, unsigned long long b, unsigned long long c) {
    unsigned long long d;
    asm("fma.rn.f32x2 %0, %1, %2, %3;" : "=l"(d) : "l"(a), "l"(b), "l"(c));
    return d;
}

// ---------------------------------------------------------------------------
// Input-projection GEMM (exact R2 structure — proven).
// ---------------------------------------------------------------------------
template <int IN, int G>
__global__ void __launch_bounds__(G, 2) gemm_xg_kernel(
    const float* __restrict__ in, const float* __restrict__ Wih,
    const float* __restrict__ bih, const float* __restrict__ bhh,
    float* __restrict__ xg)
{
    constexpr int ROWS = 128;
    __shared__ __align__(16) float sIn[ROWS * IN];

    const int g = threadIdx.x;
    const size_t row0 = (size_t)blockIdx.x * ROWS;

    {
        const float4* src = (const float4*)(in + row0 * IN);
        float4* dst = (float4*)sIn;
        constexpr int NV = ROWS * IN / 4;
        for (int i = g; i < NV; i += G) dst[i] = src[i];
    }

    unsigned long long w2[IN / 2];
    {
        const unsigned long long* wp = (const unsigned long long*)(Wih + (size_t)g * IN);
#pragma unroll
        for (int i = 0; i < IN / 2; i++) w2[i] = wp[i];
    }
    const float bias = bih[g] + bhh[g];

    __syncthreads();

    float* outp = xg + row0 * G + g;
#pragma unroll 1
    for (int r = 0; r < ROWS; r++) {
        unsigned long long accA = pk2(bias, 0.0f);
        unsigned long long accB = pk2(0.0f, 0.0f);
        const ulonglong2* rp = (const ulonglong2*)(sIn + r * IN);
#pragma unroll
        for (int i = 0; i < IN / 4; i++) {
            ulonglong2 v = rp[i];
            accA = ffma2(w2[2 * i + 0], v.x, accA);
            accB = ffma2(w2[2 * i + 1], v.y, accB);
        }
        float a0, a1, b0, b1;
        upk2(accA, a0, a1);
        upk2(accB, b0, b1);
        outp[(size_t)r * G] = (a0 + a1) + (b0 + b1);
    }
}

// ---------------------------------------------------------------------------
// Recurrent scan, generic H (64, 72): block = 4H threads = ONE batch row,
// grid = B. Thread j owns gate row j of Whh (split accA/accB chains).
// launch_bounds MINB tuned so all/most blocks are resident in one wave.
// ---------------------------------------------------------------------------
template <int H, int MINB>
__global__ void __launch_bounds__(4 * H, MINB) lstm_rec_kernel(
    const float* __restrict__ xg, const float* __restrict__ Whh,
    float* __restrict__ hout)
{
    constexpr int G4 = 4 * H;
    __shared__ __align__(16) float h_sm[H];
    __shared__ float g_sm[G4];

    const int j = threadIdx.x;
    const int b = blockIdx.x;
    const int gate = j / H;

    unsigned long long w2[H / 2];
    {
        const unsigned long long* wp = (const unsigned long long*)(Whh + (size_t)j * H);
#pragma unroll
        for (int k = 0; k < H / 2; k++) w2[k] = wp[k];
    }

    if (j < H) h_sm[j] = 0.0f;
    float c = 0.0f;

    const float* xgp = xg + (size_t)b * Tn * G4 + j;
    float* hp = hout + (size_t)b * Tn * H;

    float xn = xgp[0];
    __syncthreads();

    for (int t = 0; t < Tn; t++) {
        unsigned long long accA = pk2(xn, 0.0f);
        unsigned long long accB = pk2(0.0f, 0.0f);

        if (t + 1 < Tn) xn = xgp[(size_t)(t + 1) * G4];

        const ulonglong2* hb = (const ulonglong2*)h_sm;
#pragma unroll
        for (int k = 0; k < H / 4; k++) {
            ulonglong2 hv = hb[k];
            accA = ffma2(w2[2 * k + 0], hv.x, accA);
            accB = ffma2(w2[2 * k + 1], hv.y, accB);
        }
        float a0, a1, b0, b1;
        upk2(accA, a0, a1);
        upk2(accB, b0, b1);
        float a = (a0 + a1) + (b0 + b1);

        a = (gate == 2) ? ftanh(a) : fsig(a);
        g_sm[j] = a;
        __syncthreads();

        if (j < H) {
            const float iv = g_sm[0 * H + j];
            const float fv = g_sm[1 * H + j];
            const float gv = g_sm[2 * H + j];
            const float ov = g_sm[3 * H + j];
            c = fv * c + iv * gv;
            const float h = ov * ftanh(c);
            h_sm[j] = h;
            hp[(size_t)t * H + j] = h;
        }
        __syncthreads();
    }
}

// ---------------------------------------------------------------------------
// Recurrent scan, H=32 split-K: block = 8H = 256 threads = ONE batch row.
// Thread pair (2g, 2g+1) computes gate row g; each owns half the Whh row,
// partials combined with one shfl_xor(1). Doubles resident warps vs 4H.
// ---------------------------------------------------------------------------
__global__ void __launch_bounds__(256, 4) lstm_rec32s_kernel(
    const float* __restrict__ xg, const float* __restrict__ Whh,
    float* __restrict__ hout)
{
    constexpr int H = 32, G4 = 128;
    __shared__ __align__(16) float h_sm[H];
    __shared__ float g_sm[G4];

    const int j = threadIdx.x;
    const int g = j >> 1;      // gate row 0..127
    const int s = j & 1;       // half index
    const int b = blockIdx.x;
    const int gate = g / H;

    unsigned long long w2[H / 4];  // half a row: 16 floats = 8 u64
    {
        const unsigned long long* wp =
            (const unsigned long long*)(Whh + (size_t)g * H + s * (H / 2));
#pragma unroll
        for (int k = 0; k < H / 4; k++) w2[k] = wp[k];
    }

    if (j < H) h_sm[j] = 0.0f;
    float c = 0.0f;

    const float* xgp = xg + (size_t)b * Tn * G4 + g;
    float* hp = hout + (size_t)b * Tn * H;

    float xn = (s == 0) ? xgp[0] : 0.0f;
    __syncthreads();

    for (int t = 0; t < Tn; t++) {
        unsigned long long accA = pk2(xn, 0.0f);
        unsigned long long accB = pk2(0.0f, 0.0f);

        if (s == 0 && t + 1 < Tn) xn = xgp[(size_t)(t + 1) * G4];

        const ulonglong2* hb = (const ulonglong2*)(h_sm + s * (H / 2));
#pragma unroll
        for (int k = 0; k < H / 8; k++) {
            ulonglong2 hv = hb[k];
            accA = ffma2(w2[2 * k + 0], hv.x, accA);
            accB = ffma2(w2[2 * k + 1], hv.y, accB);
        }
        float a0, a1, b0, b1;
        upk2(accA, a0, a1);
        upk2(accB, b0, b1);
        float tot = (a0 + a1) + (b0 + b1);
        float oth = __shfl_xor_sync(0xffffffffu, tot, 1);
        float a = tot + oth;

        if (s == 0) {
            a = (gate == 2) ? ftanh(a) : fsig(a);
            g_sm[g] = a;
        }
        __syncthreads();

        if (j < H) {
            const float iv = g_sm[0 * H + j];
            const float fv = g_sm[1 * H + j];
            const float gv = g_sm[2 * H + j];
            const float ov = g_sm[3 * H + j];
            c = fv * c + iv * gv;
            const float h = ov * ftanh(c);
            h_sm[j] = h;
            hp[(size_t)t * H + j] = h;
        }
        __syncthreads();
    }
}

// ---------------------------------------------------------------------------
extern "C" void kernel_launch(void* const* d_in, const int* in_sizes, int n_in,
                              void* d_out, int out_size)
{
    (void)in_sizes; (void)n_in; (void)out_size;

    const float* x    = (const float*)d_in[0];
    const float* e1W  = (const float*)d_in[1];
    const float* e1U  = (const float*)d_in[2];
    const float* e1bi = (const float*)d_in[3];
    const float* e1bh = (const float*)d_in[4];
    const float* e2W  = (const float*)d_in[5];
    const float* e2U  = (const float*)d_in[6];
    const float* e2bi = (const float*)d_in[7];
    const float* e2bh = (const float*)d_in[8];
    const float* d1W  = (const float*)d_in[9];
    const float* d1U  = (const float*)d_in[10];
    const float* d1bi = (const float*)d_in[11];
    const float* d1bh = (const float*)d_in[12];
    const float* d2W  = (const float*)d_in[13];
    const float* d2U  = (const float*)d_in[14];
    const float* d2bi = (const float*)d_in[15];
    const float* d2bh = (const float*)d_in[16];
    float* out = (float*)d_out;

    float *xg = nullptr, *sa = nullptr, *sb = nullptr;
    cudaGetSymbolAddress((void**)&xg, g_xg);
    cudaGetSymbolAddress((void**)&sa, g_seqA);
    cudaGetSymbolAddress((void**)&sb, g_seqB);

    const int gemmGrid = (int)(BTn / 128);  // 2048

    // e1: 72 -> 64
    gemm_xg_kernel<72, 256><<<gemmGrid, 256>>>(x, e1W, e1bi, e1bh, xg);
    lstm_rec_kernel<64, 4><<<Bn, 256>>>(xg, e1U, sa);
    // e2: 64 -> 32
    gemm_xg_kernel<64, 128><<<gemmGrid, 128>>>(sa, e2W, e2bi, e2bh, xg);
    lstm_rec32s_kernel<<<Bn, 256>>>(xg, e2U, sb);
    // d1: 32 -> 64
    gemm_xg_kernel<32, 256><<<gemmGrid, 256>>>(sb, d1W, d1bi, d1bh, xg);
    lstm_rec_kernel<64, 4><<<Bn, 256>>>(xg, d1U, sa);
    // d2: 64 -> 72
    gemm_xg_kernel<64, 288><<<gemmGrid, 288>>>(sa, d2W, d2bi, d2bh, xg);
    lstm_rec_kernel<72, 3><<<Bn, 288>>>(xg, d2U, out);
}

// round 9
// speedup vs baseline: 1.8600x; 1.8600x over previous
#include <cuda_runtime.h>

static constexpr int Tn = 512;
static constexpr int Bn = 512;
static constexpr long BTn = (long)Bn * Tn;

// Scratch (device globals; allocation-free kernel_launch)
__device__ float g_xg[(size_t)512 * 512 * 288];   // max 4H = 288
__device__ float g_seqA[(size_t)512 * 512 * 64];  // e1 out / d1 out
__device__ float g_seqB[(size_t)512 * 512 * 32];  // e2 out

__device__ __forceinline__ float fsig(float x) {
    return __fdividef(1.0f, 1.0f + __expf(-x));
}
__device__ __forceinline__ float ftanh(float x) {
    return 1.0f - __fdividef(2.0f, __expf(2.0f * x) + 1.0f);
}

// ---- packed f32x2 helpers (Blackwell) ----
__device__ __forceinline__ unsigned long long pk2(float lo, float hi) {
    unsigned long long r;
    asm("mov.b64 %0, {%1, %2};" : "=l"(r) : "f"(lo), "f"(hi));
    return r;
}
__device__ __forceinline__ void upk2(unsigned long long v, float& lo, float& hi) {
    asm("mov.b64 {%0, %1}, %2;" : "=f"(lo), "=f"(hi) : "l"(v));
}
__device__ __forceinline__ unsigned long long ffma2(
    unsigned long long a, unsigned long long b, unsigned long long c) {
    unsigned long long d;
    asm("fma.rn.f32x2 %0, %1, %2, %3;" : "=l"(d) : "l"(a), "l"(b), "l"(c));
    return d;
}

// ---------------------------------------------------------------------------
// Input-projection GEMM: one gate row per thread (block = G), weights in
// packed regs, 128 input rows in SMEM (warp-uniform broadcast LDS.128).
// TWO rows per iteration -> 4 independent ffma2 chains reusing the same
// weight registers; chain latency fully hidden by issue.
// ---------------------------------------------------------------------------
template <int IN, int G>
__global__ void __launch_bounds__(G, 2) gemm_xg_kernel(
    const float* __restrict__ in, const float* __restrict__ Wih,
    const float* __restrict__ bih, const float* __restrict__ bhh,
    float* __restrict__ xg)
{
    constexpr int ROWS = 128;
    __shared__ __align__(16) float sIn[ROWS * IN];

    const int g = threadIdx.x;
    const size_t row0 = (size_t)blockIdx.x * ROWS;

    {
        const float4* src = (const float4*)(in + row0 * IN);
        float4* dst = (float4*)sIn;
        constexpr int NV = ROWS * IN / 4;
        for (int i = g; i < NV; i += G) dst[i] = src[i];
    }

    unsigned long long w2[IN / 2];
    {
        const unsigned long long* wp = (const unsigned long long*)(Wih + (size_t)g * IN);
#pragma unroll
        for (int i = 0; i < IN / 2; i++) w2[i] = wp[i];
    }
    const float bias = bih[g] + bhh[g];

    __syncthreads();

    float* outp = xg + row0 * G + g;
#pragma unroll 1
    for (int r = 0; r < ROWS; r += 2) {
        unsigned long long aA = pk2(bias, 0.0f);
        unsigned long long aB = pk2(0.0f, 0.0f);
        unsigned long long bA = pk2(bias, 0.0f);
        unsigned long long bB = pk2(0.0f, 0.0f);
        const ulonglong2* rp0 = (const ulonglong2*)(sIn + r * IN);
        const ulonglong2* rp1 = (const ulonglong2*)(sIn + (r + 1) * IN);
#pragma unroll
        for (int i = 0; i < IN / 4; i++) {
            ulonglong2 v0 = rp0[i];
            ulonglong2 v1 = rp1[i];
            aA = ffma2(w2[2 * i + 0], v0.x, aA);
            aB = ffma2(w2[2 * i + 1], v0.y, aB);
            bA = ffma2(w2[2 * i + 0], v1.x, bA);
            bB = ffma2(w2[2 * i + 1], v1.y, bB);
        }
        float x0, x1, y0, y1;
        upk2(aA, x0, x1);
        upk2(aB, y0, y1);
        outp[(size_t)r * G] = (x0 + x1) + (y0 + y1);
        upk2(bA, x0, x1);
        upk2(bB, y0, y1);
        outp[(size_t)(r + 1) * G] = (x0 + x1) + (y0 + y1);
    }
}

// ---------------------------------------------------------------------------
// Recurrent scan — EXACT round-2 structure (measured best: 2425 us total).
// Block = 4H threads, R batch rows per block, 2 barriers/step, xg prefetch,
// single accumulator chain per row. No launch_bounds-induced spill:
// MINB=2 -> 128-reg cap >= 64-reg w2 + live state.
// ---------------------------------------------------------------------------
template <int H, int R, int MINB>
__global__ void __launch_bounds__(4 * H, MINB) lstm_rec_kernel(
    const float* __restrict__ xg, const float* __restrict__ Whh,
    float* __restrict__ hout)
{
    constexpr int G4 = 4 * H;
    __shared__ __align__(16) float h_sm[R * H];
    __shared__ float g_sm[R * G4];

    const int j = threadIdx.x;
    const int b0 = blockIdx.x * R;
    const int gate = j / H;

    unsigned long long w2[H / 2];
    {
        const unsigned long long* wp = (const unsigned long long*)(Whh + (size_t)j * H);
#pragma unroll
        for (int k = 0; k < H / 2; k++) w2[k] = wp[k];
    }

    for (int i = j; i < R * H; i += G4) h_sm[i] = 0.0f;
    float c = 0.0f;

    const float* xgp = xg + (size_t)b0 * Tn * G4 + j;
    float* hp = hout + (size_t)b0 * Tn * H;

    const int cr = j / H;  // cell-update mapping (first R*H threads)
    const int cm = j % H;

    float xn[R];
#pragma unroll
    for (int r = 0; r < R; r++) xn[r] = xgp[(size_t)r * Tn * G4];

    __syncthreads();

    for (int t = 0; t < Tn; t++) {
        unsigned long long acc[R];
#pragma unroll
        for (int r = 0; r < R; r++) acc[r] = pk2(xn[r], 0.0f);

        if (t + 1 < Tn) {
#pragma unroll
            for (int r = 0; r < R; r++)
                xn[r] = xgp[((size_t)r * Tn + t + 1) * G4];
        }

#pragma unroll
        for (int k = 0; k < H / 4; k++) {
#pragma unroll
            for (int r = 0; r < R; r++) {
                ulonglong2 hv = ((const ulonglong2*)&h_sm[r * H])[k];
                acc[r] = ffma2(w2[2 * k + 0], hv.x, acc[r]);
                acc[r] = ffma2(w2[2 * k + 1], hv.y, acc[r]);
            }
        }

#pragma unroll
        for (int r = 0; r < R; r++) {
            float lo, hi;
            upk2(acc[r], lo, hi);
            float a = lo + hi;
            a = (gate == 2) ? ftanh(a) : fsig(a);
            g_sm[r * G4 + j] = a;
        }
        __syncthreads();

        if (j < R * H) {
            const float iv = g_sm[cr * G4 + 0 * H + cm];
            const float fv = g_sm[cr * G4 + 1 * H + cm];
            const float gv = g_sm[cr * G4 + 2 * H + cm];
            const float ov = g_sm[cr * G4 + 3 * H + cm];
            c = fv * c + iv * gv;
            const float h = ov * ftanh(c);
            h_sm[cr * H + cm] = h;
            hp[((size_t)cr * Tn + t) * H + cm] = h;
        }
        __syncthreads();
    }
}

// ---------------------------------------------------------------------------
extern "C" void kernel_launch(void* const* d_in, const int* in_sizes, int n_in,
                              void* d_out, int out_size)
{
    (void)in_sizes; (void)n_in; (void)out_size;

    const float* x    = (const float*)d_in[0];
    const float* e1W  = (const float*)d_in[1];
    const float* e1U  = (const float*)d_in[2];
    const float* e1bi = (const float*)d_in[3];
    const float* e1bh = (const float*)d_in[4];
    const float* e2W  = (const float*)d_in[5];
    const float* e2U  = (const float*)d_in[6];
    const float* e2bi = (const float*)d_in[7];
    const float* e2bh = (const float*)d_in[8];
    const float* d1W  = (const float*)d_in[9];
    const float* d1U  = (const float*)d_in[10];
    const float* d1bi = (const float*)d_in[11];
    const float* d1bh = (const float*)d_in[12];
    const float* d2W  = (const float*)d_in[13];
    const float* d2U  = (const float*)d_in[14];
    const float* d2bi = (const float*)d_in[15];
    const float* d2bh = (const float*)d_in[16];
    float* out = (float*)d_out;

    float *xg = nullptr, *sa = nullptr, *sb = nullptr;
    cudaGetSymbolAddress((void**)&xg, g_xg);
    cudaGetSymbolAddress((void**)&sa, g_seqA);
    cudaGetSymbolAddress((void**)&sb, g_seqB);

    const int gemmGrid = (int)(BTn / 128);  // 2048

    // e1: 72 -> 64
    gemm_xg_kernel<72, 256><<<gemmGrid, 256>>>(x, e1W, e1bi, e1bh, xg);
    lstm_rec_kernel<64, 2, 2><<<Bn / 2, 256>>>(xg, e1U, sa);
    // e2: 64 -> 32
    gemm_xg_kernel<64, 128><<<gemmGrid, 128>>>(sa, e2W, e2bi, e2bh, xg);
    lstm_rec_kernel<32, 1, 4><<<Bn, 128>>>(xg, e2U, sb);
    // d1: 32 -> 64
    gemm_xg_kernel<32, 256><<<gemmGrid, 256>>>(sb, d1W, d1bi, d1bh, xg);
    lstm_rec_kernel<64, 2, 2><<<Bn / 2, 256>>>(xg, d1U, sa);
    // d2: 64 -> 72
    gemm_xg_kernel<64, 288><<<gemmGrid, 288>>>(sa, d2W, d2bi, d2bh, xg);
    lstm_rec_kernel<72, 2, 2><<<Bn / 2, 288>>>(xg, d2U, out);
}